// round 8
// baseline (speedup 1.0000x reference)
#include <cuda_runtime.h>

// MLP_89498528514757 — fused recommender MLP, fp32. Round 8:
// ROWS=2, grid 512 x 256 threads, no min-blocks reg cap -> 3-4 independent
// resident blocks per SM (separate barrier domains) for stall hiding.
// Layer 2: 4 j/thread, 8-way split-K (32 iters). Layer 3: 2 j/thread,
// 8-way split-K (16 iters). Partials in per-row planes -> conflict-free
// combines, 8-deep only.

#define NUM_USERS 100000
#define BATCH     1024
#define ROWS      2

__global__ __launch_bounds__(256)
void mlp_fused_kernel(const int*   __restrict__ user_ids,
                      const int*   __restrict__ item_ids,
                      const float* __restrict__ W1, const float* __restrict__ b1,
                      const float* __restrict__ W2, const float* __restrict__ b2,
                      const float* __restrict__ W3, const float* __restrict__ b3,
                      const float* __restrict__ W4, const float* __restrict__ b4,
                      float*       __restrict__ out)
{
    __shared__ float2 h1t[256];                 // [k] -> 2 rows       (2 KB)
    __shared__ union {
        float l2[8][2][128];                    // [ks][row][j]        (8 KB)
        float l3[8][2][64];                     // [ks][row][j]        (4 KB)
    } P;
    __shared__ float2 h2t[128];                 // [k] -> 2 rows       (1 KB)
    __shared__ float2 h3t[64];                  // [j] -> 2 rows      (0.5 KB)

    const int t    = threadIdx.x;               // 0..255
    const int row0 = blockIdx.x * ROWS;

    // ---------------- Layer 1: dependent DRAM gather chain FIRST -----------
    const int u0 = user_ids[row0],     i0 = item_ids[row0];
    const int u1 = user_ids[row0 + 1], i1 = item_ids[row0 + 1];
    const float g0 = W1[u0 * 256 + t], e0 = W1[(NUM_USERS + i0) * 256 + t];
    const float g1 = W1[u1 * 256 + t], e1 = W1[(NUM_USERS + i1) * 256 + t];

    // ---- overlap while the gather is in flight ----------------------------
    const int jg = t & 31;                      // layer-2 j-group: j = 4*jg..
    const int kq = t >> 5;                      // 0..7 k-split (32 iters)
    const float4* __restrict__ w2p =
        reinterpret_cast<const float4*>(W2) + (kq * 32) * 32 + jg;
    float4 w2pre[4];
    #pragma unroll
    for (int i = 0; i < 4; ++i) w2pre[i] = w2p[i * 32];

    const int jp3 = t & 31;                     // layer-3 j-pair: j = 2*jp3
    const int ks3 = t >> 5;                     // 0..7 k-split (16 iters)
    const float2* __restrict__ w3p =
        reinterpret_cast<const float2*>(W3) + (ks3 * 16) * 32 + jp3;
    float2 w3pre[4];
    #pragma unroll
    for (int i = 0; i < 4; ++i) w3pre[i] = w3p[i * 32];

    const float bj2 = b2[t & 127];
    const float bj3 = b3[t & 63];
    float w4a = 0.f, w4b = 0.f, bb4 = 0.f;
    if (t < 32) { w4a = W4[t]; w4b = W4[t + 32]; bb4 = b4[0]; }

    // finish layer 1
    {
        const float bk = b1[t];
        h1t[t] = make_float2(fmaxf(g0 + e0 + bk, 0.f),
                             fmaxf(g1 + e1 + bk, 0.f));
    }
    __syncthreads();

    // ---------------- Layer 2: [2x256] @ W2[256x128], 8-way K, 4 j/thread --
    {
        float2 a0 = make_float2(0.f, 0.f);
        float2 a1 = a0, a2 = a0, a3 = a0;
        #pragma unroll
        for (int kk = 0; kk < 4; ++kk) {        // weights already in regs
            const float4 w = w2pre[kk];
            const float2 v = h1t[kq * 32 + kk]; // broadcast LDS.64
            a0.x = fmaf(v.x, w.x, a0.x); a0.y = fmaf(v.y, w.x, a0.y);
            a1.x = fmaf(v.x, w.y, a1.x); a1.y = fmaf(v.y, w.y, a1.y);
            a2.x = fmaf(v.x, w.z, a2.x); a2.y = fmaf(v.y, w.z, a2.y);
            a3.x = fmaf(v.x, w.w, a3.x); a3.y = fmaf(v.y, w.w, a3.y);
        }
        #pragma unroll
        for (int kk = 4; kk < 32; ++kk) {
            const float4 w = w2p[kk * 32];      // LDG.128, coalesced
            const float2 v = h1t[kq * 32 + kk];
            a0.x = fmaf(v.x, w.x, a0.x); a0.y = fmaf(v.y, w.x, a0.y);
            a1.x = fmaf(v.x, w.y, a1.x); a1.y = fmaf(v.y, w.y, a1.y);
            a2.x = fmaf(v.x, w.z, a2.x); a2.y = fmaf(v.y, w.z, a2.y);
            a3.x = fmaf(v.x, w.w, a3.x); a3.y = fmaf(v.y, w.w, a3.y);
        }
        // per-row planes, j-contiguous: STS.128 per row, conflict-free
        *reinterpret_cast<float4*>(&P.l2[kq][0][jg * 4]) =
            make_float4(a0.x, a1.x, a2.x, a3.x);
        *reinterpret_cast<float4*>(&P.l2[kq][1][jg * 4]) =
            make_float4(a0.y, a1.y, a2.y, a3.y);
    }
    __syncthreads();

    // combine layer-2 partials: 256 threads, (j = t&127, r = t>>7)
    {
        const int j = t & 127, r = t >> 7;
        float s = bj2;
        #pragma unroll
        for (int q = 0; q < 8; ++q) s += P.l2[q][r][j];   // LDS.32, no conflict
        reinterpret_cast<float*>(&h2t[j])[r] = fmaxf(s, 0.f);
    }
    __syncthreads();

    // ---------------- Layer 3: [2x128] @ W3[128x64], 8-way K, 2 j/thread ---
    {
        float2 a0 = make_float2(0.f, 0.f);      // j = 2*jp3   (.x row0 .y row1)
        float2 a1 = a0;                         // j = 2*jp3+1
        #pragma unroll
        for (int kk = 0; kk < 4; ++kk) {
            const float2 w = w3pre[kk];
            const float2 v = h2t[ks3 * 16 + kk];
            a0.x = fmaf(v.x, w.x, a0.x); a0.y = fmaf(v.y, w.x, a0.y);
            a1.x = fmaf(v.x, w.y, a1.x); a1.y = fmaf(v.y, w.y, a1.y);
        }
        #pragma unroll
        for (int kk = 4; kk < 16; ++kk) {
            const float2 w = w3p[kk * 32];      // LDG.64
            const float2 v = h2t[ks3 * 16 + kk];
            a0.x = fmaf(v.x, w.x, a0.x); a0.y = fmaf(v.y, w.x, a0.y);
            a1.x = fmaf(v.x, w.y, a1.x); a1.y = fmaf(v.y, w.y, a1.y);
        }
        *reinterpret_cast<float2*>(&P.l3[ks3][0][jp3 * 2]) =
            make_float2(a0.x, a1.x);
        *reinterpret_cast<float2*>(&P.l3[ks3][1][jp3 * 2]) =
            make_float2(a0.y, a1.y);
    }
    __syncthreads();

    // combine layer-3 partials: 128 threads, (j = t&63, r = t>>6)
    if (t < 128) {
        const int j = t & 63, r = t >> 6;
        float s = bj3;
        #pragma unroll
        for (int q = 0; q < 8; ++q) s += P.l3[q][r][j];
        reinterpret_cast<float*>(&h3t[j])[r] = fmaxf(s, 0.f);
    }
    __syncthreads();

    // ---------------- Layer 4: [2x64] @ W4[64x1] + b4 (warp 0) -------------
    if (t < 32) {
        const float2 va = h3t[t], vb = h3t[t + 32];
        float a0 = fmaf(va.x, w4a, vb.x * w4b);   // row 0
        float a1 = fmaf(va.y, w4a, vb.y * w4b);   // row 1
        #pragma unroll
        for (int off = 16; off > 0; off >>= 1) {
            a0 += __shfl_down_sync(0xffffffffu, a0, off);
            a1 += __shfl_down_sync(0xffffffffu, a1, off);
        }
        if (t == 0) {
            out[row0 + 0] = a0 + bb4;
            out[row0 + 1] = a1 + bb4;
        }
    }
}

extern "C" void kernel_launch(void* const* d_in, const int* in_sizes, int n_in,
                              void* d_out, int out_size)
{
    const int*   user_ids = (const int*)  d_in[0];
    const int*   item_ids = (const int*)  d_in[1];
    const float* W1       = (const float*)d_in[2];
    const float* b1       = (const float*)d_in[3];
    const float* W2       = (const float*)d_in[4];
    const float* b2       = (const float*)d_in[5];
    const float* W3       = (const float*)d_in[6];
    const float* b3       = (const float*)d_in[7];
    const float* W4       = (const float*)d_in[8];
    const float* b4       = (const float*)d_in[9];
    float*       out      = (float*)d_out;

    mlp_fused_kernel<<<BATCH / ROWS, 256>>>(user_ids, item_ids,
                                            W1, b1, W2, b2, W3, b3, W4, b4, out);
}

// round 9
// speedup vs baseline: 1.3411x; 1.3411x over previous
#include <cuda_runtime.h>

// MLP_89498528514757 — fused recommender MLP, fp32. Round 9:
// R5 skeleton (grid 256 x 512, 2 blocks/SM, ROWS=4, 4-way L2 / 8-way L3
// split-K) + group-local pipelining: each 4-warp group gathers exactly the
// h1 k-slice its layer-2 split needs and syncs on a NAMED barrier
// (bar.sync kq+1, 128) instead of a global one — groups run skewed, so
// W2 L2-loads of running groups overlap DRAM gathers of slower ones.
// Partials stored as float4[slice][j]: conflict-free STS.128 + combine.

#define NUM_USERS 100000
#define BATCH     1024
#define ROWS      4

__global__ __launch_bounds__(512, 2)
void mlp_fused_kernel(const int*   __restrict__ user_ids,
                      const int*   __restrict__ item_ids,
                      const float* __restrict__ W1, const float* __restrict__ b1,
                      const float* __restrict__ W2, const float* __restrict__ b2,
                      const float* __restrict__ W3, const float* __restrict__ b3,
                      const float* __restrict__ W4, const float* __restrict__ b4,
                      float*       __restrict__ out)
{
    __shared__ float4 h1t[256];                 // [k] -> 4 rows       (4 KB)
    __shared__ union {
        float4 l2[4][128];                      // [slice][j] -> rows  (8 KB)
        float4 l3[8][64];                       // [slice][j] -> rows  (4 KB)
    } P;
    __shared__ float4 h2t[128];                 // [k] -> rows         (2 KB)
    __shared__ float4 h3t[64];                  // [j] -> rows         (1 KB)

    const int t    = threadIdx.x;               // 0..511
    const int row0 = blockIdx.x * ROWS;

    const int q  = t & 127;                     // id within group
    const int kq = t >> 7;                      // group = layer-2 k-slice (0..3)

    // ---------------- Layer 1 (group-local): gather OWN k-slice ------------
    // Group kq produces h1[64kq .. 64kq+64) x 4 rows. Thread: k = 64kq+(q>>1),
    // rows {rb, rb+1} with rb = (q&1)*2.  4 dependent DRAM/L2 gathers.
    const int k1 = 64 * kq + (q >> 1);
    const int rb = (q & 1) * 2;
    const int ua = user_ids[row0 + rb],     ia = item_ids[row0 + rb];
    const int ub = user_ids[row0 + rb + 1], ib = item_ids[row0 + rb + 1];
    const float ga = W1[ua * 256 + k1], ea = W1[(NUM_USERS + ia) * 256 + k1];
    const float gb = W1[ub * 256 + k1], eb = W1[(NUM_USERS + ib) * 256 + k1];

    // ---- overlap while gather is in flight: W2/W3 prefetch, biases --------
    const int j2 = q;                           // layer-2 output column
    const float* __restrict__ w2p = W2 + (kq * 64) * 128 + j2;
    float w2pre[16];
    #pragma unroll
    for (int i = 0; i < 16; ++i) w2pre[i] = w2p[i * 128];

    const int j3 = t & 63;
    const int k8 = t >> 6;                      // layer-3 k-slice (0..7)
    float w3pre[16];
    {
        const float* __restrict__ w3p = W3 + (k8 * 16) * 64 + j3;
        #pragma unroll
        for (int i = 0; i < 16; ++i) w3pre[i] = w3p[i * 64];
    }

    const float bj2 = b2[t >> 2];               // combine2: j = t>>2
    const float bj3 = b3[(t >> 2) & 63];        // combine3: j = t>>2 (t<256)
    float w4a = 0.f, w4b = 0.f, bb4 = 0.f;
    if (t < 32) { w4a = W4[t]; w4b = W4[t + 32]; bb4 = b4[0]; }

    // finish own h1 entries (STS.64, conflict-free: addr = k*16 + rb*4)
    {
        const float bk = b1[k1];
        float2 h;
        h.x = fmaxf(ga + ea + bk, 0.f);
        h.y = fmaxf(gb + eb + bk, 0.f);
        *reinterpret_cast<float2*>(
            reinterpret_cast<float*>(&h1t[k1]) + rb) = h;
    }
    // group-local barrier: only this slice's 4 warps wait
    asm volatile("bar.sync %0, %1;" :: "r"(kq + 1), "r"(128) : "memory");

    // ---------------- Layer 2: [4x256] @ W2[256x128], 4-way split-K --------
    {
        float4 a = make_float4(0.f, 0.f, 0.f, 0.f);
        #pragma unroll
        for (int kk = 0; kk < 16; ++kk) {       // weights already in regs
            const float  w = w2pre[kk];
            const float4 v = h1t[kq * 64 + kk]; // broadcast LDS.128
            a.x = fmaf(v.x, w, a.x);  a.y = fmaf(v.y, w, a.y);
            a.z = fmaf(v.z, w, a.z);  a.w = fmaf(v.w, w, a.w);
        }
        #pragma unroll
        for (int kk = 16; kk < 64; ++kk) {
            const float  w = w2p[kk * 128];     // coalesced LDG (L2)
            const float4 v = h1t[kq * 64 + kk];
            a.x = fmaf(v.x, w, a.x);  a.y = fmaf(v.y, w, a.y);
            a.z = fmaf(v.z, w, a.z);  a.w = fmaf(v.w, w, a.w);
        }
        P.l2[kq][j2] = a;                       // STS.128, lanes j-contiguous
    }
    __syncthreads();

    // combine layer-2 partials: 512 threads, element (j = t>>2, r = t&3)
    {
        const int j = t >> 2, r = t & 3;
        float s = bj2;
        #pragma unroll
        for (int p = 0; p < 4; ++p)             // LDS.32, lane-consecutive
            s += reinterpret_cast<const float*>(&P.l2[p][j])[r];
        reinterpret_cast<float*>(&h2t[j])[r] = fmaxf(s, 0.f);
    }
    __syncthreads();

    // ---------------- Layer 3: [4x128] @ W3[128x64], 8-way split-K ---------
    {
        float4 a = make_float4(0.f, 0.f, 0.f, 0.f);
        #pragma unroll
        for (int kk = 0; kk < 16; ++kk) {
            const float  w = w3pre[kk];
            const float4 v = h2t[k8 * 16 + kk];
            a.x = fmaf(v.x, w, a.x);  a.y = fmaf(v.y, w, a.y);
            a.z = fmaf(v.z, w, a.z);  a.w = fmaf(v.w, w, a.w);
        }
        P.l3[k8][j3] = a;
    }
    __syncthreads();

    // combine layer-3 partials: 256 threads, element (j = t>>2, r = t&3)
    if (t < 256) {
        const int j = t >> 2, r = t & 3;
        float s = bj3;
        #pragma unroll
        for (int p = 0; p < 8; ++p)
            s += reinterpret_cast<const float*>(&P.l3[p][j])[r];
        reinterpret_cast<float*>(&h3t[j])[r] = fmaxf(s, 0.f);
    }
    __syncthreads();

    // ---------------- Layer 4: [4x64] @ W4[64x1] + b4 (warp 0) -------------
    if (t < 32) {
        const float4 va = h3t[t], vb = h3t[t + 32];
        float a0 = fmaf(va.x, w4a, vb.x * w4b);
        float a1 = fmaf(va.y, w4a, vb.y * w4b);
        float a2 = fmaf(va.z, w4a, vb.z * w4b);
        float a3 = fmaf(va.w, w4a, vb.w * w4b);
        #pragma unroll
        for (int off = 16; off > 0; off >>= 1) {
            a0 += __shfl_down_sync(0xffffffffu, a0, off);
            a1 += __shfl_down_sync(0xffffffffu, a1, off);
            a2 += __shfl_down_sync(0xffffffffu, a2, off);
            a3 += __shfl_down_sync(0xffffffffu, a3, off);
        }
        if (t == 0) {
            out[row0 + 0] = a0 + bb4;
            out[row0 + 1] = a1 + bb4;
            out[row0 + 2] = a2 + bb4;
            out[row0 + 3] = a3 + bb4;
        }
    }
}

extern "C" void kernel_launch(void* const* d_in, const int* in_sizes, int n_in,
                              void* d_out, int out_size)
{
    const int*   user_ids = (const int*)  d_in[0];
    const int*   item_ids = (const int*)  d_in[1];
    const float* W1       = (const float*)d_in[2];
    const float* b1       = (const float*)d_in[3];
    const float* W2       = (const float*)d_in[4];
    const float* b2       = (const float*)d_in[5];
    const float* W3       = (const float*)d_in[6];
    const float* b3       = (const float*)d_in[7];
    const float* W4       = (const float*)d_in[8];
    const float* b4       = (const float*)d_in[9];
    float*       out      = (float*)d_out;

    mlp_fused_kernel<<<BATCH / ROWS, 512>>>(user_ids, item_ids,
                                            W1, b1, W2, b2, W3, b3, W4, b4, out);
}